// round 16
// baseline (speedup 1.0000x reference)
#include <cuda_runtime.h>
#include <cuda_fp16.h>
#include <math.h>

#define N_NODES 100000
#define E_EDGES 1600000
#define E2      (E_EDGES + N_NODES)   // 1,700,000
#define IN_C    128
#define HID     64
#define HEADS   4
#define HH      (HEADS * HID)         // 256
#define OUT_C   2
#define NEG_SLOPE 0.2f
#define NB_SCAN ((N_NODES + 1023) / 1024)   // 98

struct Edge { int src; float norm; };

// ---------------- scratch ----------------------------------------------------
__device__ __align__(16) int    g_degi[N_NODES];
__device__ __align__(16) int    g_cnt[N_NODES];
__device__ __align__(16) int    g_rowptr[N_NODES + 1];
__device__ __align__(16) int    g_bsum[NB_SCAN];
__device__ __align__(16) int    g_boff[NB_SCAN];
__device__ __align__(16) float  g_dinv[N_NODES];
__device__ __align__(16) Edge   g_csr[E2];
__device__ __align__(16) __half g_wh[(size_t)E2 * HEADS];        // fp16 softmax weights
__device__ __align__(16) float  g_inv[(size_t)N_NODES * HEADS];  // 1/den per node/head
__device__ __align__(16) __half g_xw1h[(size_t)N_NODES * HID];
__device__ __align__(16) float  g_h0 [(size_t)N_NODES * HID];
__device__ __align__(16) __half g_xw2h[(size_t)N_NODES * HH];    // 51MB
__device__ __align__(16) float  g_as [(size_t)N_NODES * HEADS];
__device__ __align__(16) float  g_ad [(size_t)N_NODES * HEADS];
__device__ __align__(16) float  g_mx[8];
__device__ __align__(16) float  g_hw3[(size_t)N_NODES * OUT_C];

__device__ __forceinline__ float lrelu(float x) { return x > 0.0f ? x : NEG_SLOPE * x; }

__device__ __forceinline__ void atomicMaxFloat(float* addr, float value) {
    if (value >= 0.0f) atomicMax((int*)addr, __float_as_int(value));
    else               atomicMin((unsigned int*)addr, __float_as_uint(value));
}

// ---------------- CSR build --------------------------------------------------
__global__ void k_init() {
    int i = blockIdx.x * blockDim.x + threadIdx.x;
    if (i < N_NODES) { g_degi[i] = 0; g_cnt[i] = 0; }
    if (i < 8) g_mx[i] = -3.402823466e38f;
}

__global__ void k_edges(const int* __restrict__ ei) {
    int t = blockIdx.x * blockDim.x + threadIdx.x;
    int e0 = t * 2;
    if (e0 >= E2) return;
    int d0 = (e0 < E_EDGES) ? ei[E_EDGES + e0] : (e0 - E_EDGES);
    atomicAdd(&g_degi[d0], 1);
    int e1 = e0 + 1;
    if (e1 < E2) {
        int d1 = (e1 < E_EDGES) ? ei[E_EDGES + e1] : (e1 - E_EDGES);
        atomicAdd(&g_degi[d1], 1);
    }
}

__global__ void k_scanA() {
    __shared__ int sh[1024];
    int t = threadIdx.x;
    int i = blockIdx.x * 1024 + t;
    int deg = (i < N_NODES) ? g_degi[i] : 0;
    sh[t] = deg;
    __syncthreads();
    #pragma unroll
    for (int off = 1; off < 1024; off <<= 1) {
        int v = (t >= off) ? sh[t - off] : 0;
        __syncthreads();
        sh[t] += v;
        __syncthreads();
    }
    if (i < N_NODES) {
        g_rowptr[i] = sh[t] - deg;
        g_dinv[i] = deg > 0 ? rsqrtf((float)deg) : 0.0f;
    }
    if (t == 1023) g_bsum[blockIdx.x] = sh[1023];
}

__global__ void k_scanB() {
    __shared__ int sh[128];
    int t = threadIdx.x;
    int v = (t < NB_SCAN) ? g_bsum[t] : 0;
    sh[t] = v;
    __syncthreads();
    #pragma unroll
    for (int off = 1; off < 128; off <<= 1) {
        int u = (t >= off) ? sh[t - off] : 0;
        __syncthreads();
        sh[t] += u;
        __syncthreads();
    }
    if (t < NB_SCAN) g_boff[t] = sh[t] - v;
}

__global__ void k_scanC() {
    int i = blockIdx.x * blockDim.x + threadIdx.x;
    if (i < N_NODES) g_rowptr[i] += g_boff[i >> 10];
    if (i == 0) g_rowptr[N_NODES] = E2;
}

__global__ void k_fill(const int* __restrict__ ei) {
    int e = blockIdx.x * blockDim.x + threadIdx.x;
    if (e >= E2) return;
    int s, d;
    if (e < E_EDGES) { s = ei[e]; d = ei[E_EDGES + e]; }
    else             { s = e - E_EDGES; d = s; }
    int pos = g_rowptr[d] + atomicAdd(&g_cnt[d], 1);
    Edge ed; ed.src = s; ed.norm = g_dinv[s] * g_dinv[d];
    g_csr[pos] = ed;
}

// ---------------- GEMM 1: xw1h = fp16(x @ W1) -------------------------------
__global__ void __launch_bounds__(256) k_gemm1(const float* __restrict__ x,
                                               const float* __restrict__ W1) {
    __shared__ __align__(16) float As[64][68];
    __shared__ __align__(16) float Bs[64][HID];
    int tid = threadIdx.x;
    int tx = tid & 15, ty = tid >> 4;
    int row0 = blockIdx.x * 64;
    float acc[4][4];
    #pragma unroll
    for (int i = 0; i < 4; i++)
        #pragma unroll
        for (int j = 0; j < 4; j++) acc[i][j] = 0.0f;

    for (int kc = 0; kc < IN_C; kc += 64) {
        __syncthreads();
        #pragma unroll
        for (int it = 0; it < 4; it++) {
            int idx = tid + it * 256;
            int r = idx >> 4, k4 = idx & 15;
            int row = row0 + r;
            float4 v = make_float4(0.f, 0.f, 0.f, 0.f);
            if (row < N_NODES)
                v = *(const float4*)&x[(size_t)row * IN_C + kc + k4 * 4];
            *(float4*)&As[r][k4 * 4] = v;
        }
        #pragma unroll
        for (int it = 0; it < 4; it++) {
            int idx = tid + it * 256;
            int k = idx >> 4, c4 = idx & 15;
            *(float4*)&Bs[k][c4 * 4] = *(const float4*)&W1[(size_t)(kc + k) * HID + c4 * 4];
        }
        __syncthreads();
        #pragma unroll 16
        for (int k = 0; k < 64; k++) {
            float a0 = As[ty * 4 + 0][k], a1 = As[ty * 4 + 1][k];
            float a2 = As[ty * 4 + 2][k], a3 = As[ty * 4 + 3][k];
            float4 b = *(const float4*)&Bs[k][tx * 4];
            acc[0][0] += a0 * b.x; acc[0][1] += a0 * b.y; acc[0][2] += a0 * b.z; acc[0][3] += a0 * b.w;
            acc[1][0] += a1 * b.x; acc[1][1] += a1 * b.y; acc[1][2] += a1 * b.z; acc[1][3] += a1 * b.w;
            acc[2][0] += a2 * b.x; acc[2][1] += a2 * b.y; acc[2][2] += a2 * b.z; acc[2][3] += a2 * b.w;
            acc[3][0] += a3 * b.x; acc[3][1] += a3 * b.y; acc[3][2] += a3 * b.z; acc[3][3] += a3 * b.w;
        }
    }
    #pragma unroll
    for (int i = 0; i < 4; i++) {
        int row = row0 + ty * 4 + i;
        if (row < N_NODES) {
            __half2 p0 = __floats2half2_rn(acc[i][0], acc[i][1]);
            __half2 p1 = __floats2half2_rn(acc[i][2], acc[i][3]);
            uint2 u; u.x = *(unsigned*)&p0; u.y = *(unsigned*)&p1;
            *(uint2*)&g_xw1h[(size_t)row * HID + tx * 4] = u;
        }
    }
}

// ---------------- GCN-1 gather: 2 warps per node, EDGE-split ---------------
// block 256 = 8 warps = 4 nodes (grid 25000 exact). Each warp covers all 64
// channels (float2/lane) over HALF the edge range; combine in smem.
__global__ void __launch_bounds__(256) k_gcn1(const float* __restrict__ b1) {
    __shared__ float sH[8][HID];
    int tid = threadIdx.x;
    int wl = tid >> 5;
    int nodeLocal = wl >> 1;
    int node = blockIdx.x * 4 + nodeLocal;
    int half = wl & 1;
    int lane = tid & 31;
    int r0 = g_rowptr[node], r1 = g_rowptr[node + 1];
    int mid = r0 + ((r1 - r0 + 1) >> 1);
    int ea = half ? mid : r0;
    int eb = half ? r1 : mid;

    float acc0 = 0.0f, acc1 = 0.0f;
    int off = lane * 2;
    int e = ea;
    for (; e + 4 <= eb; e += 4) {
        Edge e0 = g_csr[e], e1 = g_csr[e + 1], e2 = g_csr[e + 2], e3 = g_csr[e + 3];
        __half2 h0 = *(const __half2*)&g_xw1h[(size_t)e0.src * HID + off];
        __half2 h1 = *(const __half2*)&g_xw1h[(size_t)e1.src * HID + off];
        __half2 h2 = *(const __half2*)&g_xw1h[(size_t)e2.src * HID + off];
        __half2 h3 = *(const __half2*)&g_xw1h[(size_t)e3.src * HID + off];
        float2 v0 = __half22float2(h0), v1 = __half22float2(h1);
        float2 v2 = __half22float2(h2), v3 = __half22float2(h3);
        acc0 += v0.x * e0.norm + v1.x * e1.norm + v2.x * e2.norm + v3.x * e3.norm;
        acc1 += v0.y * e0.norm + v1.y * e1.norm + v2.y * e2.norm + v3.y * e3.norm;
    }
    for (; e < eb; e++) {
        Edge ed = g_csr[e];
        float2 v = __half22float2(*(const __half2*)&g_xw1h[(size_t)ed.src * HID + off]);
        acc0 += v.x * ed.norm; acc1 += v.y * ed.norm;
    }
    sH[wl][off] = acc0; sH[wl][off + 1] = acc1;
    __syncthreads();
    if (half == 0) {                              // even warp writes output
        float2 o;
        o.x = fmaxf(sH[wl][off]     + sH[wl + 1][off]     + __ldg(&b1[off]),     0.0f);
        o.y = fmaxf(sH[wl][off + 1] + sH[wl + 1][off + 1] + __ldg(&b1[off + 1]), 0.0f);
        *(float2*)&g_h0[(size_t)node * HID + off] = o;
    }
}

// ---------------- GEMM 2: xw2h = fp16(h0 @ W2), attn dots + fused global max
__global__ void __launch_bounds__(256) k_gemm2(const float* __restrict__ W2,
                                               const float* __restrict__ attS,
                                               const float* __restrict__ attD) {
    __shared__ __align__(16) float As[64][68];
    __shared__ __align__(16) float Bs[64][64];
    __shared__ float sa[64], sd[64];
    __shared__ float redS[64], redD[64];
    int tid = threadIdx.x;
    int tx = tid & 15, ty = tid >> 4;
    int head = blockIdx.y;
    int row0 = blockIdx.x * 64;

    #pragma unroll
    for (int it = 0; it < 4; it++) {
        int idx = tid + it * 256;
        int r = idx >> 4, k4 = idx & 15;
        int row = row0 + r;
        float4 v = make_float4(0.f, 0.f, 0.f, 0.f);
        if (row < N_NODES)
            v = *(const float4*)&g_h0[(size_t)row * HID + k4 * 4];
        *(float4*)&As[r][k4 * 4] = v;
    }
    #pragma unroll
    for (int it = 0; it < 4; it++) {
        int idx = tid + it * 256;
        int k = idx >> 4, c4 = idx & 15;
        *(float4*)&Bs[k][c4 * 4] =
            *(const float4*)&W2[(size_t)k * HH + head * 64 + c4 * 4];
    }
    if (tid < 64) { sa[tid] = attS[head * 64 + tid]; sd[tid] = attD[head * 64 + tid]; }
    __syncthreads();

    float acc[4][4];
    #pragma unroll
    for (int i = 0; i < 4; i++)
        #pragma unroll
        for (int j = 0; j < 4; j++) acc[i][j] = 0.0f;

    #pragma unroll 16
    for (int k = 0; k < 64; k++) {
        float a0 = As[ty * 4 + 0][k], a1 = As[ty * 4 + 1][k];
        float a2 = As[ty * 4 + 2][k], a3 = As[ty * 4 + 3][k];
        float4 b = *(const float4*)&Bs[k][tx * 4];
        acc[0][0] += a0 * b.x; acc[0][1] += a0 * b.y; acc[0][2] += a0 * b.z; acc[0][3] += a0 * b.w;
        acc[1][0] += a1 * b.x; acc[1][1] += a1 * b.y; acc[1][2] += a1 * b.z; acc[1][3] += a1 * b.w;
        acc[2][0] += a2 * b.x; acc[2][1] += a2 * b.y; acc[2][2] += a2 * b.z; acc[2][3] += a2 * b.w;
        acc[3][0] += a3 * b.x; acc[3][1] += a3 * b.y; acc[3][2] += a3 * b.z; acc[3][3] += a3 * b.w;
    }

    #pragma unroll
    for (int i = 0; i < 4; i++) {
        int row = row0 + ty * 4 + i;
        if (row < N_NODES) {
            __half2 p0 = __floats2half2_rn(acc[i][0], acc[i][1]);
            __half2 p1 = __floats2half2_rn(acc[i][2], acc[i][3]);
            uint2 u; u.x = *(unsigned*)&p0; u.y = *(unsigned*)&p1;
            *(uint2*)&g_xw2h[(size_t)row * HH + head * 64 + tx * 4] = u;
        }
    }

    float ps[4], pd[4];
    #pragma unroll
    for (int i = 0; i < 4; i++) {
        float s = 0.f, d = 0.f;
        #pragma unroll
        for (int j = 0; j < 4; j++) {
            s += acc[i][j] * sa[tx * 4 + j];
            d += acc[i][j] * sd[tx * 4 + j];
        }
        ps[i] = s; pd[i] = d;
    }
    #pragma unroll
    for (int off = 8; off >= 1; off >>= 1) {
        #pragma unroll
        for (int i = 0; i < 4; i++) {
            ps[i] += __shfl_xor_sync(0xffffffffu, ps[i], off);
            pd[i] += __shfl_xor_sync(0xffffffffu, pd[i], off);
        }
    }
    float ms = fmaxf(fmaxf(ps[0], ps[1]), fmaxf(ps[2], ps[3]));
    float md = fmaxf(fmaxf(pd[0], pd[1]), fmaxf(pd[2], pd[3]));
    if (tx == 0) {
        #pragma unroll
        for (int i = 0; i < 4; i++) {
            int row = row0 + ty * 4 + i;
            if (row < N_NODES) {
                g_as[(size_t)row * HEADS + head] = ps[i];
                g_ad[(size_t)row * HEADS + head] = pd[i];
            }
        }
        redS[ty] = ms; redD[ty] = md;
    }
    __syncthreads();
    if (tid < 32) {
        float vs = (tid < 16) ? redS[tid] : -3.4e38f;
        float vd = (tid < 16) ? redD[tid] : -3.4e38f;
        #pragma unroll
        for (int o = 8; o >= 1; o >>= 1) {
            vs = fmaxf(vs, __shfl_xor_sync(0xffffffffu, vs, o));
            vd = fmaxf(vd, __shfl_xor_sync(0xffffffffu, vd, o));
        }
        if (tid == 0) {
            atomicMaxFloat(&g_mx[head],     vs);
            atomicMaxFloat(&g_mx[head + 4], vd);
        }
    }
}

// ---------------- warp-per-node softmax weights (fp16) + 1/den -------------
__global__ void k_weight() {
    int node = (blockIdx.x * blockDim.x + threadIdx.x) >> 5;
    int lane = threadIdx.x & 31;
    if (node >= N_NODES) return;
    float C0 = lrelu(g_mx[0] + g_mx[4]);
    float C1 = lrelu(g_mx[1] + g_mx[5]);
    float C2 = lrelu(g_mx[2] + g_mx[6]);
    float C3 = lrelu(g_mx[3] + g_mx[7]);
    float4 b = *(const float4*)&g_ad[(size_t)node * HEADS];
    int r0 = g_rowptr[node], r1 = g_rowptr[node + 1];
    float d0 = 0.f, d1 = 0.f, d2 = 0.f, d3 = 0.f;
    for (int e = r0 + lane; e < r1; e += 32) {
        int s = g_csr[e].src;
        float4 a = *(const float4*)&g_as[(size_t)s * HEADS];
        __half2 wlo = __floats2half2_rn(__expf(lrelu(a.x + b.x) - C0),
                                        __expf(lrelu(a.y + b.y) - C1));
        __half2 whi = __floats2half2_rn(__expf(lrelu(a.z + b.z) - C2),
                                        __expf(lrelu(a.w + b.w) - C3));
        uint2 uu; uu.x = *(unsigned*)&wlo; uu.y = *(unsigned*)&whi;
        *(uint2*)&g_wh[(size_t)e * HEADS] = uu;
        float2 flo = __half22float2(wlo), fhi = __half22float2(whi);
        d0 += flo.x; d1 += flo.y; d2 += fhi.x; d3 += fhi.y;
    }
    #pragma unroll
    for (int o = 16; o >= 1; o >>= 1) {
        d0 += __shfl_xor_sync(0xffffffffu, d0, o);
        d1 += __shfl_xor_sync(0xffffffffu, d1, o);
        d2 += __shfl_xor_sync(0xffffffffu, d2, o);
        d3 += __shfl_xor_sync(0xffffffffu, d3, o);
    }
    if (lane == 0) {
        float4 iv;
        iv.x = 1.0f / d0; iv.y = 1.0f / d1;
        iv.z = 1.0f / d2; iv.w = 1.0f / d3;
        *(float4*)&g_inv[(size_t)node * HEADS] = iv;
    }
}

// ---------------- fused GAT: 2 warps per node, EDGE-split ------------------
// Each warp covers all 256 channels (uint4 = 8 fp16/lane) over half the edge
// range; csr/wh loaded once per edge per warp-half; combine in smem.
__global__ void __launch_bounds__(256) k_gat(const float* __restrict__ b2,
                                             const float* __restrict__ W3) {
    __shared__ float sW3[HH * 2];
    __shared__ float sb2[HH];
    __shared__ float sAcc[8][HH];
    __shared__ float sPart[8][2];
    int tid = threadIdx.x;
    sW3[tid * 2]     = W3[tid * 2];
    sW3[tid * 2 + 1] = W3[tid * 2 + 1];
    sb2[tid]         = b2[tid];
    __syncthreads();

    int wl = tid >> 5;
    int nodeLocal = wl >> 1;
    int node = blockIdx.x * 4 + nodeLocal;
    int half = wl & 1;
    int lane = tid & 31;
    int r0 = g_rowptr[node], r1 = g_rowptr[node + 1];
    int mid = r0 + ((r1 - r0 + 1) >> 1);
    int ea = half ? mid : r0;
    int eb = half ? r1 : mid;

    int colBase = lane * 8;                      // 8 fp16 channels per lane
    int headq = lane >> 3;                       // lanes 0-7 head0, ... 24-31 head3

    float acc[8];
    #pragma unroll
    for (int j = 0; j < 8; j++) acc[j] = 0.0f;

    int e = ea;
    for (; e + 4 <= eb; e += 4) {
        int s0 = g_csr[e].src,     s1 = g_csr[e + 1].src;
        int s2 = g_csr[e + 2].src, s3 = g_csr[e + 3].src;
        uint2 wp0 = *(const uint2*)&g_wh[(size_t)(e)     * HEADS];
        uint2 wp1 = *(const uint2*)&g_wh[(size_t)(e + 1) * HEADS];
        uint2 wp2 = *(const uint2*)&g_wh[(size_t)(e + 2) * HEADS];
        uint2 wp3 = *(const uint2*)&g_wh[(size_t)(e + 3) * HEADS];
        uint4 u0 = *(const uint4*)&g_xw2h[(size_t)s0 * HH + colBase];
        uint4 u1 = *(const uint4*)&g_xw2h[(size_t)s1 * HH + colBase];
        uint4 u2 = *(const uint4*)&g_xw2h[(size_t)s2 * HH + colBase];
        uint4 u3 = *(const uint4*)&g_xw2h[(size_t)s3 * HH + colBase];
        #pragma unroll
        for (int j = 0; j < 4; j++) {
            uint2 wp = (j == 0) ? wp0 : (j == 1) ? wp1 : (j == 2) ? wp2 : wp3;
            uint4 u  = (j == 0) ? u0  : (j == 1) ? u1  : (j == 2) ? u2  : u3;
            unsigned wsel = (headq < 2) ? wp.x : wp.y;
            float2 wf = __half22float2(*(__half2*)&wsel);
            float w = (headq & 1) ? wf.y : wf.x;
            float2 f;
            f = __half22float2(*(__half2*)&u.x); acc[0] += f.x * w; acc[1] += f.y * w;
            f = __half22float2(*(__half2*)&u.y); acc[2] += f.x * w; acc[3] += f.y * w;
            f = __half22float2(*(__half2*)&u.z); acc[4] += f.x * w; acc[5] += f.y * w;
            f = __half22float2(*(__half2*)&u.w); acc[6] += f.x * w; acc[7] += f.y * w;
        }
    }
    for (; e < eb; e++) {
        int s = g_csr[e].src;
        uint2 wp = *(const uint2*)&g_wh[(size_t)e * HEADS];
        unsigned wsel = (headq < 2) ? wp.x : wp.y;
        float2 wf = __half22float2(*(__half2*)&wsel);
        float w = (headq & 1) ? wf.y : wf.x;
        uint4 u = *(const uint4*)&g_xw2h[(size_t)s * HH + colBase];
        float2 f;
        f = __half22float2(*(__half2*)&u.x); acc[0] += f.x * w; acc[1] += f.y * w;
        f = __half22float2(*(__half2*)&u.y); acc[2] += f.x * w; acc[3] += f.y * w;
        f = __half22float2(*(__half2*)&u.z); acc[4] += f.x * w; acc[5] += f.y * w;
        f = __half22float2(*(__half2*)&u.w); acc[6] += f.x * w; acc[7] += f.y * w;
    }
    #pragma unroll
    for (int j = 0; j < 8; j++) sAcc[wl][colBase + j] = acc[j];
    __syncthreads();

    // epilogue: warp pair covers 256 channels; this warp does its 128-half
    int col  = half * 128 + lane * 4;
    int head = col >> 6;
    float inv = g_inv[(size_t)node * HEADS + head];
    int wb = nodeLocal * 2;
    float a0 = 0.0f, a1 = 0.0f;
    #pragma unroll
    for (int j = 0; j < 4; j++) {
        int c = col + j;
        float v = (sAcc[wb][c] + sAcc[wb + 1][c]) * inv + sb2[c];
        v = v > 0.0f ? v : expm1f(v);
        a0 += v * sW3[c * 2];
        a1 += v * sW3[c * 2 + 1];
    }
    #pragma unroll
    for (int o = 16; o >= 1; o >>= 1) {
        a0 += __shfl_xor_sync(0xffffffffu, a0, o);
        a1 += __shfl_xor_sync(0xffffffffu, a1, o);
    }
    if (lane == 0) { sPart[wl][0] = a0; sPart[wl][1] = a1; }
    __syncthreads();
    if (tid < 4) {
        int n = blockIdx.x * 4 + tid;
        g_hw3[(size_t)n * 2]     = sPart[tid * 2][0] + sPart[tid * 2 + 1][0];
        g_hw3[(size_t)n * 2 + 1] = sPart[tid * 2][1] + sPart[tid * 2 + 1][1];
    }
}

// ---------------- GCN-2 gather ----------------------------------------------
__global__ void k_gcn2(const float* __restrict__ b3, float* __restrict__ out) {
    int warp = (blockIdx.x * blockDim.x + threadIdx.x) >> 5;
    int lane = threadIdx.x & 31;
    if (warp >= N_NODES) return;
    int r0 = g_rowptr[warp], r1 = g_rowptr[warp + 1];
    float acc0 = 0.0f, acc1 = 0.0f;
    for (int e = r0 + lane; e < r1; e += 32) {
        Edge ed = g_csr[e];
        float2 v = *(const float2*)&g_hw3[(size_t)ed.src * 2];
        acc0 += v.x * ed.norm; acc1 += v.y * ed.norm;
    }
    #pragma unroll
    for (int o = 16; o >= 1; o >>= 1) {
        acc0 += __shfl_xor_sync(0xffffffffu, acc0, o);
        acc1 += __shfl_xor_sync(0xffffffffu, acc1, o);
    }
    if (lane == 0) {
        out[(size_t)warp * 2]     = acc0 + __ldg(&b3[0]);
        out[(size_t)warp * 2 + 1] = acc1 + __ldg(&b3[1]);
    }
}

// ---------------- launch -------------------------------------------------------
extern "C" void kernel_launch(void* const* d_in, const int* in_sizes, int n_in,
                              void* d_out, int out_size) {
    const float* x    = (const float*)d_in[0];
    const int*   ei   = (const int*)d_in[1];
    const float* W1   = (const float*)d_in[2];
    const float* b1   = (const float*)d_in[3];
    const float* W2   = (const float*)d_in[4];
    const float* attS = (const float*)d_in[5];
    const float* attD = (const float*)d_in[6];
    const float* b2   = (const float*)d_in[7];
    const float* W3   = (const float*)d_in[8];
    const float* b3   = (const float*)d_in[9];
    float* out = (float*)d_out;

    const int T = 256;
    const int RB = (N_NODES + 63) / 64;

    k_gemm1 <<<RB, T>>>(x, W1);
    k_init  <<<(N_NODES + T - 1) / T, T>>>();
    k_edges <<<(E2 / 2 + T - 1) / T, T>>>(ei);
    k_scanA <<<NB_SCAN, 1024>>>();
    k_scanB <<<1, 128>>>();
    k_scanC <<<(N_NODES + T - 1) / T, T>>>();
    k_fill  <<<(E2 + T - 1) / T, T>>>(ei);
    k_gcn1  <<<N_NODES / 4, T>>>(b1);
    k_gemm2 <<<dim3(RB, HEADS), T>>>(W2, attS, attD);
    k_weight<<<(N_NODES * 32 + T - 1) / T, T>>>();
    k_gat   <<<N_NODES / 4, T>>>(b2, W3);
    k_gcn2  <<<(N_NODES * 32 + T - 1) / T, T>>>(b3, out);
}

// round 17
// speedup vs baseline: 1.0840x; 1.0840x over previous
#include <cuda_runtime.h>
#include <cuda_fp16.h>
#include <math.h>

#define N_NODES 100000
#define E_EDGES 1600000
#define E2      (E_EDGES + N_NODES)   // 1,700,000
#define IN_C    128
#define HID     64
#define HEADS   4
#define HH      (HEADS * HID)         // 256
#define OUT_C   2
#define NEG_SLOPE 0.2f
#define NB_SCAN ((N_NODES + 1023) / 1024)   // 98

struct Edge { int src; float norm; };

// ---------------- scratch ----------------------------------------------------
__device__ __align__(16) int    g_degi[N_NODES];
__device__ __align__(16) int    g_cnt[N_NODES];
__device__ __align__(16) int    g_rowptr[N_NODES + 1];
__device__ __align__(16) int    g_bsum[NB_SCAN];
__device__ __align__(16) int    g_boff[NB_SCAN];
__device__ __align__(16) float  g_dinv[N_NODES];
__device__ __align__(16) Edge   g_csr[E2];
__device__ __align__(16) __half g_wh[(size_t)E2 * HEADS];        // fp16 softmax weights
__device__ __align__(16) float  g_inv[(size_t)N_NODES * HEADS];  // 1/den per node/head
__device__ __align__(16) __half g_xw1h[(size_t)N_NODES * HID];
__device__ __align__(16) float  g_h0 [(size_t)N_NODES * HID];
__device__ __align__(16) __half g_xw2h[(size_t)N_NODES * HH];    // 51MB
__device__ __align__(16) float  g_as [(size_t)N_NODES * HEADS];
__device__ __align__(16) float  g_ad [(size_t)N_NODES * HEADS];
__device__ __align__(16) float  g_mx[8];
__device__ __align__(16) float  g_hw3[(size_t)N_NODES * OUT_C];

__device__ __forceinline__ float lrelu(float x) { return x > 0.0f ? x : NEG_SLOPE * x; }

__device__ __forceinline__ void atomicMaxFloat(float* addr, float value) {
    if (value >= 0.0f) atomicMax((int*)addr, __float_as_int(value));
    else               atomicMin((unsigned int*)addr, __float_as_uint(value));
}

// ---------------- CSR build --------------------------------------------------
__global__ void k_init() {
    int i = blockIdx.x * blockDim.x + threadIdx.x;
    if (i < N_NODES) { g_degi[i] = 0; g_cnt[i] = 0; }
    if (i < 8) g_mx[i] = -3.402823466e38f;
}

__global__ void k_edges(const int* __restrict__ ei) {
    int t = blockIdx.x * blockDim.x + threadIdx.x;
    int e0 = t * 2;
    if (e0 >= E2) return;
    int d0 = (e0 < E_EDGES) ? ei[E_EDGES + e0] : (e0 - E_EDGES);
    atomicAdd(&g_degi[d0], 1);
    int e1 = e0 + 1;
    if (e1 < E2) {
        int d1 = (e1 < E_EDGES) ? ei[E_EDGES + e1] : (e1 - E_EDGES);
        atomicAdd(&g_degi[d1], 1);
    }
}

__global__ void k_scanA() {
    __shared__ int sh[1024];
    int t = threadIdx.x;
    int i = blockIdx.x * 1024 + t;
    int deg = (i < N_NODES) ? g_degi[i] : 0;
    sh[t] = deg;
    __syncthreads();
    #pragma unroll
    for (int off = 1; off < 1024; off <<= 1) {
        int v = (t >= off) ? sh[t - off] : 0;
        __syncthreads();
        sh[t] += v;
        __syncthreads();
    }
    if (i < N_NODES) {
        g_rowptr[i] = sh[t] - deg;
        g_dinv[i] = deg > 0 ? rsqrtf((float)deg) : 0.0f;
    }
    if (t == 1023) g_bsum[blockIdx.x] = sh[1023];
}

__global__ void k_scanB() {
    __shared__ int sh[128];
    int t = threadIdx.x;
    int v = (t < NB_SCAN) ? g_bsum[t] : 0;
    sh[t] = v;
    __syncthreads();
    #pragma unroll
    for (int off = 1; off < 128; off <<= 1) {
        int u = (t >= off) ? sh[t - off] : 0;
        __syncthreads();
        sh[t] += u;
        __syncthreads();
    }
    if (t < NB_SCAN) g_boff[t] = sh[t] - v;
}

__global__ void k_scanC() {
    int i = blockIdx.x * blockDim.x + threadIdx.x;
    if (i < N_NODES) g_rowptr[i] += g_boff[i >> 10];
    if (i == 0) g_rowptr[N_NODES] = E2;
}

__global__ void k_fill(const int* __restrict__ ei) {
    int e = blockIdx.x * blockDim.x + threadIdx.x;
    if (e >= E2) return;
    int s, d;
    if (e < E_EDGES) { s = ei[e]; d = ei[E_EDGES + e]; }
    else             { s = e - E_EDGES; d = s; }
    int pos = g_rowptr[d] + atomicAdd(&g_cnt[d], 1);
    Edge ed; ed.src = s; ed.norm = g_dinv[s] * g_dinv[d];
    g_csr[pos] = ed;
}

// ---------------- GEMM 1: xw1h = fp16(x @ W1) -------------------------------
__global__ void __launch_bounds__(256) k_gemm1(const float* __restrict__ x,
                                               const float* __restrict__ W1) {
    __shared__ __align__(16) float As[64][68];
    __shared__ __align__(16) float Bs[64][HID];
    int tid = threadIdx.x;
    int tx = tid & 15, ty = tid >> 4;
    int row0 = blockIdx.x * 64;
    float acc[4][4];
    #pragma unroll
    for (int i = 0; i < 4; i++)
        #pragma unroll
        for (int j = 0; j < 4; j++) acc[i][j] = 0.0f;

    for (int kc = 0; kc < IN_C; kc += 64) {
        __syncthreads();
        #pragma unroll
        for (int it = 0; it < 4; it++) {
            int idx = tid + it * 256;
            int r = idx >> 4, k4 = idx & 15;
            int row = row0 + r;
            float4 v = make_float4(0.f, 0.f, 0.f, 0.f);
            if (row < N_NODES)
                v = *(const float4*)&x[(size_t)row * IN_C + kc + k4 * 4];
            *(float4*)&As[r][k4 * 4] = v;
        }
        #pragma unroll
        for (int it = 0; it < 4; it++) {
            int idx = tid + it * 256;
            int k = idx >> 4, c4 = idx & 15;
            *(float4*)&Bs[k][c4 * 4] = *(const float4*)&W1[(size_t)(kc + k) * HID + c4 * 4];
        }
        __syncthreads();
        #pragma unroll 16
        for (int k = 0; k < 64; k++) {
            float a0 = As[ty * 4 + 0][k], a1 = As[ty * 4 + 1][k];
            float a2 = As[ty * 4 + 2][k], a3 = As[ty * 4 + 3][k];
            float4 b = *(const float4*)&Bs[k][tx * 4];
            acc[0][0] += a0 * b.x; acc[0][1] += a0 * b.y; acc[0][2] += a0 * b.z; acc[0][3] += a0 * b.w;
            acc[1][0] += a1 * b.x; acc[1][1] += a1 * b.y; acc[1][2] += a1 * b.z; acc[1][3] += a1 * b.w;
            acc[2][0] += a2 * b.x; acc[2][1] += a2 * b.y; acc[2][2] += a2 * b.z; acc[2][3] += a2 * b.w;
            acc[3][0] += a3 * b.x; acc[3][1] += a3 * b.y; acc[3][2] += a3 * b.z; acc[3][3] += a3 * b.w;
        }
    }
    #pragma unroll
    for (int i = 0; i < 4; i++) {
        int row = row0 + ty * 4 + i;
        if (row < N_NODES) {
            __half2 p0 = __floats2half2_rn(acc[i][0], acc[i][1]);
            __half2 p1 = __floats2half2_rn(acc[i][2], acc[i][3]);
            uint2 u; u.x = *(unsigned*)&p0; u.y = *(unsigned*)&p1;
            *(uint2*)&g_xw1h[(size_t)row * HID + tx * 4] = u;
        }
    }
}

// ---------------- GCN-1 gather (fp16, 4-unroll, warp per node) -------------
__global__ void k_gcn1(const float* __restrict__ b1) {
    int warp = (blockIdx.x * blockDim.x + threadIdx.x) >> 5;
    int lane = threadIdx.x & 31;
    if (warp >= N_NODES) return;
    int r0 = g_rowptr[warp], r1 = g_rowptr[warp + 1];
    float acc0 = 0.0f, acc1 = 0.0f;
    int off = lane * 2;
    int e = r0;
    for (; e + 4 <= r1; e += 4) {
        Edge e0 = g_csr[e], e1 = g_csr[e + 1], e2 = g_csr[e + 2], e3 = g_csr[e + 3];
        __half2 h0 = *(const __half2*)&g_xw1h[(size_t)e0.src * HID + off];
        __half2 h1 = *(const __half2*)&g_xw1h[(size_t)e1.src * HID + off];
        __half2 h2 = *(const __half2*)&g_xw1h[(size_t)e2.src * HID + off];
        __half2 h3 = *(const __half2*)&g_xw1h[(size_t)e3.src * HID + off];
        float2 v0 = __half22float2(h0), v1 = __half22float2(h1);
        float2 v2 = __half22float2(h2), v3 = __half22float2(h3);
        acc0 += v0.x * e0.norm + v1.x * e1.norm + v2.x * e2.norm + v3.x * e3.norm;
        acc1 += v0.y * e0.norm + v1.y * e1.norm + v2.y * e2.norm + v3.y * e3.norm;
    }
    for (; e < r1; e++) {
        Edge ed = g_csr[e];
        float2 v = __half22float2(*(const __half2*)&g_xw1h[(size_t)ed.src * HID + off]);
        acc0 += v.x * ed.norm; acc1 += v.y * ed.norm;
    }
    float2 o;
    o.x = fmaxf(acc0 + __ldg(&b1[off]),     0.0f);
    o.y = fmaxf(acc1 + __ldg(&b1[off + 1]), 0.0f);
    *(float2*)&g_h0[(size_t)warp * HID + off] = o;
}

// ---------------- GEMM 2: one block = 64 rows x ALL 4 heads ----------------
// A tile loaded once; per head: B slice, 4x4 accs, fp16 store, attn dots + max.
__global__ void __launch_bounds__(256) k_gemm2(const float* __restrict__ W2,
                                               const float* __restrict__ attS,
                                               const float* __restrict__ attD) {
    __shared__ __align__(16) float As[64][68];
    __shared__ __align__(16) float Bs[64][64];
    __shared__ float sa[64], sd[64];
    __shared__ float redS[16], redD[16];
    int tid = threadIdx.x;
    int tx = tid & 15, ty = tid >> 4;
    int row0 = blockIdx.x * 64;

    #pragma unroll
    for (int it = 0; it < 4; it++) {
        int idx = tid + it * 256;
        int r = idx >> 4, k4 = idx & 15;
        int row = row0 + r;
        float4 v = make_float4(0.f, 0.f, 0.f, 0.f);
        if (row < N_NODES)
            v = *(const float4*)&g_h0[(size_t)row * HID + k4 * 4];
        *(float4*)&As[r][k4 * 4] = v;
    }

    for (int head = 0; head < HEADS; head++) {
        __syncthreads();
        #pragma unroll
        for (int it = 0; it < 4; it++) {
            int idx = tid + it * 256;
            int k = idx >> 4, c4 = idx & 15;
            *(float4*)&Bs[k][c4 * 4] =
                *(const float4*)&W2[(size_t)k * HH + head * 64 + c4 * 4];
        }
        if (tid < 64) { sa[tid] = attS[head * 64 + tid]; sd[tid] = attD[head * 64 + tid]; }
        __syncthreads();

        float acc[4][4];
        #pragma unroll
        for (int i = 0; i < 4; i++)
            #pragma unroll
            for (int j = 0; j < 4; j++) acc[i][j] = 0.0f;

        #pragma unroll 16
        for (int k = 0; k < 64; k++) {
            float a0 = As[ty * 4 + 0][k], a1 = As[ty * 4 + 1][k];
            float a2 = As[ty * 4 + 2][k], a3 = As[ty * 4 + 3][k];
            float4 b = *(const float4*)&Bs[k][tx * 4];
            acc[0][0] += a0 * b.x; acc[0][1] += a0 * b.y; acc[0][2] += a0 * b.z; acc[0][3] += a0 * b.w;
            acc[1][0] += a1 * b.x; acc[1][1] += a1 * b.y; acc[1][2] += a1 * b.z; acc[1][3] += a1 * b.w;
            acc[2][0] += a2 * b.x; acc[2][1] += a2 * b.y; acc[2][2] += a2 * b.z; acc[2][3] += a2 * b.w;
            acc[3][0] += a3 * b.x; acc[3][1] += a3 * b.y; acc[3][2] += a3 * b.z; acc[3][3] += a3 * b.w;
        }

        #pragma unroll
        for (int i = 0; i < 4; i++) {
            int row = row0 + ty * 4 + i;
            if (row < N_NODES) {
                __half2 p0 = __floats2half2_rn(acc[i][0], acc[i][1]);
                __half2 p1 = __floats2half2_rn(acc[i][2], acc[i][3]);
                uint2 u; u.x = *(unsigned*)&p0; u.y = *(unsigned*)&p1;
                *(uint2*)&g_xw2h[(size_t)row * HH + head * 64 + tx * 4] = u;
            }
        }

        float ps[4], pd[4];
        #pragma unroll
        for (int i = 0; i < 4; i++) {
            float s = 0.f, d = 0.f;
            #pragma unroll
            for (int j = 0; j < 4; j++) {
                s += acc[i][j] * sa[tx * 4 + j];
                d += acc[i][j] * sd[tx * 4 + j];
            }
            ps[i] = s; pd[i] = d;
        }
        #pragma unroll
        for (int off = 8; off >= 1; off >>= 1) {
            #pragma unroll
            for (int i = 0; i < 4; i++) {
                ps[i] += __shfl_xor_sync(0xffffffffu, ps[i], off);
                pd[i] += __shfl_xor_sync(0xffffffffu, pd[i], off);
            }
        }
        float ms = fmaxf(fmaxf(ps[0], ps[1]), fmaxf(ps[2], ps[3]));
        float md = fmaxf(fmaxf(pd[0], pd[1]), fmaxf(pd[2], pd[3]));
        if (tx == 0) {
            #pragma unroll
            for (int i = 0; i < 4; i++) {
                int row = row0 + ty * 4 + i;
                if (row < N_NODES) {
                    g_as[(size_t)row * HEADS + head] = ps[i];
                    g_ad[(size_t)row * HEADS + head] = pd[i];
                }
            }
            redS[ty] = ms; redD[ty] = md;
        }
        __syncthreads();
        if (tid < 32) {
            float vs = (tid < 16) ? redS[tid] : -3.4e38f;
            float vd = (tid < 16) ? redD[tid] : -3.4e38f;
            #pragma unroll
            for (int o = 8; o >= 1; o >>= 1) {
                vs = fmaxf(vs, __shfl_xor_sync(0xffffffffu, vs, o));
                vd = fmaxf(vd, __shfl_xor_sync(0xffffffffu, vd, o));
            }
            if (tid == 0) {
                atomicMaxFloat(&g_mx[head],     vs);
                atomicMaxFloat(&g_mx[head + 4], vd);
            }
        }
    }
}

// ---------------- warp-per-node softmax weights (fp16) + 1/den -------------
__global__ void k_weight() {
    int node = (blockIdx.x * blockDim.x + threadIdx.x) >> 5;
    int lane = threadIdx.x & 31;
    if (node >= N_NODES) return;
    float C0 = lrelu(g_mx[0] + g_mx[4]);
    float C1 = lrelu(g_mx[1] + g_mx[5]);
    float C2 = lrelu(g_mx[2] + g_mx[6]);
    float C3 = lrelu(g_mx[3] + g_mx[7]);
    float4 b = *(const float4*)&g_ad[(size_t)node * HEADS];
    int r0 = g_rowptr[node], r1 = g_rowptr[node + 1];
    float d0 = 0.f, d1 = 0.f, d2 = 0.f, d3 = 0.f;
    for (int e = r0 + lane; e < r1; e += 32) {
        int s = g_csr[e].src;
        float4 a = *(const float4*)&g_as[(size_t)s * HEADS];
        __half2 wlo = __floats2half2_rn(__expf(lrelu(a.x + b.x) - C0),
                                        __expf(lrelu(a.y + b.y) - C1));
        __half2 whi = __floats2half2_rn(__expf(lrelu(a.z + b.z) - C2),
                                        __expf(lrelu(a.w + b.w) - C3));
        uint2 uu; uu.x = *(unsigned*)&wlo; uu.y = *(unsigned*)&whi;
        *(uint2*)&g_wh[(size_t)e * HEADS] = uu;
        float2 flo = __half22float2(wlo), fhi = __half22float2(whi);
        d0 += flo.x; d1 += flo.y; d2 += fhi.x; d3 += fhi.y;
    }
    #pragma unroll
    for (int o = 16; o >= 1; o >>= 1) {
        d0 += __shfl_xor_sync(0xffffffffu, d0, o);
        d1 += __shfl_xor_sync(0xffffffffu, d1, o);
        d2 += __shfl_xor_sync(0xffffffffu, d2, o);
        d3 += __shfl_xor_sync(0xffffffffu, d3, o);
    }
    if (lane == 0) {
        float4 iv;
        iv.x = 1.0f / d0; iv.y = 1.0f / d1;
        iv.z = 1.0f / d2; iv.w = 1.0f / d3;
        *(float4*)&g_inv[(size_t)node * HEADS] = iv;
    }
}

// ---------------- fused GAT: 2 warps per node (channel-split), fp16 w ------
__global__ void __launch_bounds__(256) k_gat(const float* __restrict__ b2,
                                             const float* __restrict__ W3) {
    __shared__ float sW3[HH * 2];
    __shared__ float sb2[HH];
    __shared__ float sPart[8][2];
    int tid = threadIdx.x;
    sW3[tid * 2]     = W3[tid * 2];
    sW3[tid * 2 + 1] = W3[tid * 2 + 1];
    sb2[tid]         = b2[tid];
    __syncthreads();

    int wlocal = tid >> 5;
    int node   = blockIdx.x * 4 + (wlocal >> 1);
    int hpart  = wlocal & 1;
    int lane   = tid & 31;
    int r0 = g_rowptr[node], r1 = g_rowptr[node + 1];

    int col  = hpart * 128 + lane * 4;
    int head = col >> 6;
    bool hiHead = (lane & 16) != 0;
    float inv = g_inv[(size_t)node * HEADS + head];

    float acc[4];
    #pragma unroll
    for (int j = 0; j < 4; j++) acc[j] = 0.0f;

    const __half* wb = g_wh + hpart * 2;
    int e = r0;
    for (; e + 4 <= r1; e += 4) {
        int s0 = g_csr[e].src,     s1 = g_csr[e + 1].src;
        int s2 = g_csr[e + 2].src, s3 = g_csr[e + 3].src;
        unsigned wp0 = *(const unsigned*)&wb[(size_t)(e)     * HEADS];
        unsigned wp1 = *(const unsigned*)&wb[(size_t)(e + 1) * HEADS];
        unsigned wp2 = *(const unsigned*)&wb[(size_t)(e + 2) * HEADS];
        unsigned wp3 = *(const unsigned*)&wb[(size_t)(e + 3) * HEADS];
        uint2 u0 = *(const uint2*)&g_xw2h[(size_t)s0 * HH + col];
        uint2 u1 = *(const uint2*)&g_xw2h[(size_t)s1 * HH + col];
        uint2 u2 = *(const uint2*)&g_xw2h[(size_t)s2 * HH + col];
        uint2 u3 = *(const uint2*)&g_xw2h[(size_t)s3 * HH + col];
        float2 wf0 = __half22float2(*(__half2*)&wp0);
        float2 wf1 = __half22float2(*(__half2*)&wp1);
        float2 wf2 = __half22float2(*(__half2*)&wp2);
        float2 wf3 = __half22float2(*(__half2*)&wp3);
        float w0 = hiHead ? wf0.y : wf0.x;
        float w1 = hiHead ? wf1.y : wf1.x;
        float w2 = hiHead ? wf2.y : wf2.x;
        float w3 = hiHead ? wf3.y : wf3.x;
        float2 f;
        f = __half22float2(*(__half2*)&u0.x); acc[0] += f.x * w0; acc[1] += f.y * w0;
        f = __half22float2(*(__half2*)&u0.y); acc[2] += f.x * w0; acc[3] += f.y * w0;
        f = __half22float2(*(__half2*)&u1.x); acc[0] += f.x * w1; acc[1] += f.y * w1;
        f = __half22float2(*(__half2*)&u1.y); acc[2] += f.x * w1; acc[3] += f.y * w1;
        f = __half22float2(*(__half2*)&u2.x); acc[0] += f.x * w2; acc[1] += f.y * w2;
        f = __half22float2(*(__half2*)&u2.y); acc[2] += f.x * w2; acc[3] += f.y * w2;
        f = __half22float2(*(__half2*)&u3.x); acc[0] += f.x * w3; acc[1] += f.y * w3;
        f = __half22float2(*(__half2*)&u3.y); acc[2] += f.x * w3; acc[3] += f.y * w3;
    }
    for (; e < r1; e++) {
        int s = g_csr[e].src;
        unsigned wp = *(const unsigned*)&wb[(size_t)e * HEADS];
        float2 wf = __half22float2(*(__half2*)&wp);
        float w = hiHead ? wf.y : wf.x;
        uint2 u = *(const uint2*)&g_xw2h[(size_t)s * HH + col];
        float2 f;
        f = __half22float2(*(__half2*)&u.x); acc[0] += f.x * w; acc[1] += f.y * w;
        f = __half22float2(*(__half2*)&u.y); acc[2] += f.x * w; acc[3] += f.y * w;
    }

    float a0 = 0.0f, a1 = 0.0f;
    #pragma unroll
    for (int j = 0; j < 4; j++) {
        int c = col + j;
        float v = acc[j] * inv + sb2[c];
        v = v > 0.0f ? v : expm1f(v);
        a0 += v * sW3[c * 2];
        a1 += v * sW3[c * 2 + 1];
    }
    #pragma unroll
    for (int o = 16; o >= 1; o >>= 1) {
        a0 += __shfl_xor_sync(0xffffffffu, a0, o);
        a1 += __shfl_xor_sync(0xffffffffu, a1, o);
    }
    if (lane == 0) { sPart[wlocal][0] = a0; sPart[wlocal][1] = a1; }
    __syncthreads();
    if (tid < 4) {
        int n = blockIdx.x * 4 + tid;
        g_hw3[(size_t)n * 2]     = sPart[tid * 2][0] + sPart[tid * 2 + 1][0];
        g_hw3[(size_t)n * 2 + 1] = sPart[tid * 2][1] + sPart[tid * 2 + 1][1];
    }
}

// ---------------- GCN-2 gather ----------------------------------------------
__global__ void k_gcn2(const float* __restrict__ b3, float* __restrict__ out) {
    int warp = (blockIdx.x * blockDim.x + threadIdx.x) >> 5;
    int lane = threadIdx.x & 31;
    if (warp >= N_NODES) return;
    int r0 = g_rowptr[warp], r1 = g_rowptr[warp + 1];
    float acc0 = 0.0f, acc1 = 0.0f;
    for (int e = r0 + lane; e < r1; e += 32) {
        Edge ed = g_csr[e];
        float2 v = *(const float2*)&g_hw3[(size_t)ed.src * 2];
        acc0 += v.x * ed.norm; acc1 += v.y * ed.norm;
    }
    #pragma unroll
    for (int o = 16; o >= 1; o >>= 1) {
        acc0 += __shfl_xor_sync(0xffffffffu, acc0, o);
        acc1 += __shfl_xor_sync(0xffffffffu, acc1, o);
    }
    if (lane == 0) {
        out[(size_t)warp * 2]     = acc0 + __ldg(&b3[0]);
        out[(size_t)warp * 2 + 1] = acc1 + __ldg(&b3[1]);
    }
}

// ---------------- launch -------------------------------------------------------
extern "C" void kernel_launch(void* const* d_in, const int* in_sizes, int n_in,
                              void* d_out, int out_size) {
    const float* x    = (const float*)d_in[0];
    const int*   ei   = (const int*)d_in[1];
    const float* W1   = (const float*)d_in[2];
    const float* b1   = (const float*)d_in[3];
    const float* W2   = (const float*)d_in[4];
    const float* attS = (const float*)d_in[5];
    const float* attD = (const float*)d_in[6];
    const float* b2   = (const float*)d_in[7];
    const float* W3   = (const float*)d_in[8];
    const float* b3   = (const float*)d_in[9];
    float* out = (float*)d_out;

    const int T = 256;
    const int RB = (N_NODES + 63) / 64;

    k_gemm1 <<<RB, T>>>(x, W1);
    k_init  <<<(N_NODES + T - 1) / T, T>>>();
    k_edges <<<(E2 / 2 + T - 1) / T, T>>>(ei);
    k_scanA <<<NB_SCAN, 1024>>>();
    k_scanB <<<1, 128>>>();
    k_scanC <<<(N_NODES + T - 1) / T, T>>>();
    k_fill  <<<(E2 + T - 1) / T, T>>>(ei);
    k_gcn1  <<<(N_NODES * 32 + T - 1) / T, T>>>(b1);
    k_gemm2 <<<RB, T>>>(W2, attS, attD);
    k_weight<<<(N_NODES * 32 + T - 1) / T, T>>>();
    k_gat   <<<N_NODES / 4, T>>>(b2, W3);
    k_gcn2  <<<(N_NODES * 32 + T - 1) / T, T>>>(b3, out);
}